// round 13
// baseline (speedup 1.0000x reference)
#include <cuda_runtime.h>
#include <cuda_fp16.h>
#include <cstdint>
#include <cstddef>

#define SEQ    2048
#define BATCH  2
#define DMODEL 1024
#define NHEADS 16
#define DHEAD  64
#define MROWS  (BATCH*SEQ)

// ---------------- scratch (device globals; allocation-free rule) ------------
__device__ __half g_Xh  [(size_t)MROWS*DMODEL];
__device__ __half g_BTh [(size_t)DMODEL*DMODEL];           // basis^T
__device__ __half g_Bmh [(size_t)DMODEL*DMODEL];           // basis
__device__ __half g_Bqkv[(size_t)3*DMODEL*DMODEL];         // basis*sq | *sk | *sv
__device__ __half g_BTso[(size_t)DMODEL*DMODEL];           // basis^T row-scaled by so
__device__ __half g_XBh [(size_t)MROWS*DMODEL];
__device__ __half g_QKV [(size_t)3*MROWS*DMODEL];          // Q | K | V
__device__ __half g_AOh [(size_t)MROWS*DMODEL];
__device__ __half g_O1h [(size_t)MROWS*DMODEL];

// ---------------------------------------------------------------------------
__device__ __forceinline__ uint32_t smem_u32(const void* p) {
    uint32_t a;
    asm("{ .reg .u64 t; cvta.to.shared.u64 t, %1; cvt.u32.u64 %0, t; }"
        : "=r"(a) : "l"(p));
    return a;
}

#define LDMX4(r0, r1, r2, r3, addr) \
    asm volatile("ldmatrix.sync.aligned.m8n8.x4.shared.b16 {%0,%1,%2,%3}, [%4];" \
                 : "=r"(r0), "=r"(r1), "=r"(r2), "=r"(r3) : "r"(addr))

#define LDMX4T(r0, r1, r2, r3, addr) \
    asm volatile("ldmatrix.sync.aligned.m8n8.x4.trans.shared.b16 {%0,%1,%2,%3}, [%4];" \
                 : "=r"(r0), "=r"(r1), "=r"(r2), "=r"(r3) : "r"(addr))

#define MMA16816_2(d, a, b0r, b1r) \
    asm volatile("mma.sync.aligned.m16n8k16.row.col.f32.f16.f16.f32 " \
                 "{%0,%1,%2,%3}, {%4,%5,%6,%7}, {%8,%9}, {%0,%1,%2,%3};" \
                 : "+f"((d)[0]), "+f"((d)[1]), "+f"((d)[2]), "+f"((d)[3]) \
                 : "r"((a)[0]), "r"((a)[1]), "r"((a)[2]), "r"((a)[3]), \
                   "r"(b0r), "r"(b1r))

#define CPASYNC16(dst, src) \
    asm volatile("cp.async.cg.shared.global [%0], [%1], 16;" \
                 :: "r"(dst), "l"(src))
#define CPCOMMIT()  asm volatile("cp.async.commit_group;" ::: "memory")
#define CPWAIT(n)   asm volatile("cp.async.wait_group %0;" :: "n"(n) : "memory")

// XOR swizzle for 128B rows: chunk(0..7) ^= row&7 -> conflict-free ldmatrix
__device__ __forceinline__ uint32_t swz128(uint32_t o) {
    return o ^ (((o >> 7) & 7u) << 4);
}

__device__ __forceinline__ uint32_t packh(float a, float b) {
    __half x = __float2half(a), y = __float2half(b);
    return (uint32_t)__half_as_ushort(x) | ((uint32_t)__half_as_ushort(y) << 16);
}

__device__ __forceinline__ void trunc_store(void* hp, float4 v) {
    uint2 hu;
    hu.x = packh(v.x, v.y);
    hu.y = packh(v.z, v.w);
    *reinterpret_cast<uint2*>(hp) = hu;
}

// 2^y via FMA-pipe polynomial (no MUFU)
__device__ __forceinline__ float exp2p(float y) {
    y = fmaxf(y, -120.f);
    float t = y + 12582912.f;
    int   n = (__float_as_int(t) & 0x7FFFFF) - 0x400000;
    float f = y - (t - 12582912.f);
    float p = 1.3333558146e-3f;
    p = fmaf(p, f, 9.6181291076e-3f);
    p = fmaf(p, f, 5.5504108664e-2f);
    p = fmaf(p, f, 2.4022650695e-1f);
    p = fmaf(p, f, 6.9314718056e-1f);
    p = fmaf(p, f, 1.0f);
    return __int_as_float(__float_as_int(p) + (n << 23));
}

// ---------------------------------------------------------------------------
// Pre-truncate / pre-scale helpers
// ---------------------------------------------------------------------------
__global__ void trunc_plain(const float4* __restrict__ in, __half* __restrict__ h) {
    size_t i = (size_t)blockIdx.x * 256 + threadIdx.x;
    trunc_store(h + 4 * i, in[i]);
}

// basis row-major [n,k]; emit three copies with columns scaled by sq/sk/sv (k)
__global__ void trunc_scale3(const float4* __restrict__ in,
                             const float4* __restrict__ sq,
                             const float4* __restrict__ sk,
                             const float4* __restrict__ sv,
                             __half* __restrict__ bq, __half* __restrict__ bk,
                             __half* __restrict__ bv) {
    size_t i = (size_t)blockIdx.x * 256 + threadIdx.x;
    const int k4 = (int)(i & 255);               // 1024 floats per row = 256 float4
    float4 v = in[i];
    float4 a = sq[k4], b = sk[k4], c = sv[k4];
    trunc_store(bq + 4 * i, make_float4(v.x * a.x, v.y * a.y, v.z * a.z, v.w * a.w));
    trunc_store(bk + 4 * i, make_float4(v.x * b.x, v.y * b.y, v.z * b.z, v.w * b.w));
    trunc_store(bv + 4 * i, make_float4(v.x * c.x, v.y * c.y, v.z * c.z, v.w * c.w));
}

// out[n,k] = basis[k,n] * (scale ? scale[n] : 1)
__global__ void trans_trunc(const float* __restrict__ in, __half* __restrict__ oh,
                            const float* __restrict__ scale) {
    __shared__ float t[32][33];
    int bx = blockIdx.x * 32, by = blockIdx.y * 32;
    #pragma unroll
    for (int i = 0; i < 32; i += 8)
        t[threadIdx.y + i][threadIdx.x] = in[(size_t)(by + threadIdx.y + i) * DMODEL + bx + threadIdx.x];
    __syncthreads();
    #pragma unroll
    for (int i = 0; i < 32; i += 8) {
        const int n = bx + threadIdx.y + i;
        float v = t[threadIdx.x][threadIdx.y + i];
        if (scale) v *= scale[n];
        oh[(size_t)n * DMODEL + by + threadIdx.x] = __float2half(v);
    }
}

// ---------------------------------------------------------------------------
// Single-fp16 mma.sync GEMM: C[m,n] = sum_k A[m,k]*B[n,k].
// Tile 128x64, BK=64, warp tile 32x32 (4m x 2n warps), 3-stage cp.async,
// 128B-row swizzle, 3 CTAs/SM. Stage = A(16K)|B(8K) = 24KB.
// blockIdx.z batches over B/P segments (QKV). EPI: 0=fp32 C; 4=fp16 P.
// ---------------------------------------------------------------------------
static constexpr int STAGE_B  = 24576;
static constexpr int SMEM_DYN = 3 * STAGE_B;     // 73728; 3 CTAs/SM = 221KB

template<int EPI>
__global__ __launch_bounds__(256, 3)
void gemm_fp16(const __half* __restrict__ A, const __half* __restrict__ Bmat,
               float* __restrict__ C, __half* __restrict__ P,
               size_t bStride, size_t oStride)
{
    extern __shared__ char smem[];
    const __half* Bp = Bmat + (size_t)blockIdx.z * bStride;
    const size_t oofs = (size_t)blockIdx.z * oStride;

    const int tid  = threadIdx.x;
    const int lane = tid & 31;
    const int wid  = tid >> 5;
    const int bm   = blockIdx.y * 128;
    const int bn   = blockIdx.x * 64;
    const int wm0  = (wid & 3) * 32;
    const int wn0  = (wid >> 2) * 32;
    const uint32_t sbase = smem_u32(smem);

    // cp.async: A 128 rows x 128B (4 chunks/thr), B 64 rows x 128B (2 chunks/thr)
    const int arow = tid >> 1;
    const int acb  = (tid & 1) * 4;
    const int brow = tid >> 2;
    const int bcb  = (tid & 3) * 2;

    const char* gA = (const char*)A  + (size_t)(bm + arow) * 2048 + acb * 16;
    const char* gB = (const char*)Bp + (size_t)(bn + brow) * 2048 + bcb * 16;
    uint32_t soA[4], soB[2];
    #pragma unroll
    for (int i = 0; i < 4; ++i)
        soA[i] = swz128((uint32_t)(arow * 128 + (acb + i) * 16));
    #pragma unroll
    for (int i = 0; i < 2; ++i)
        soB[i] = swz128((uint32_t)(brow * 128 + (bcb + i) * 16));

    auto issue_stage = [&](int c, int s) {
        const size_t k0b = (size_t)c * 128;
        const uint32_t st = sbase + (uint32_t)s * STAGE_B;
        #pragma unroll
        for (int i = 0; i < 4; ++i)
            CPASYNC16(st + soA[i], gA + k0b + i * 16);
        #pragma unroll
        for (int i = 0; i < 2; ++i)
            CPASYNC16(st + 16384u + soB[i], gB + k0b + i * 16);
        CPCOMMIT();
    };

    float acc[2][4][4];
    #pragma unroll
    for (int i = 0; i < 2; ++i)
        #pragma unroll
        for (int j = 0; j < 4; ++j)
            #pragma unroll
            for (int q = 0; q < 4; ++q) acc[i][j][q] = 0.f;

    uint32_t aoff[2], boff[2];
    #pragma unroll
    for (int mt = 0; mt < 2; ++mt)
        aoff[mt] = (uint32_t)((wm0 + mt * 16 + (lane & 15)) * 128 + ((lane >> 4) << 4));
    #pragma unroll
    for (int bb = 0; bb < 2; ++bb)
        boff[bb] = (uint32_t)((wn0 + bb * 16 + (lane & 7) + ((lane >> 4) << 3)) * 128 + ((lane & 8) << 1));

    auto compute = [&](int s) {
        const uint32_t st = sbase + (uint32_t)s * STAGE_B;
        #pragma unroll
        for (int ks = 0; ks < 4; ++ks) {
            const uint32_t kb = ks * 32u;
            uint32_t af[2][4], bf[2][4];
            #pragma unroll
            for (int mt = 0; mt < 2; ++mt)
                LDMX4(af[mt][0], af[mt][1], af[mt][2], af[mt][3],
                      st + swz128(aoff[mt] + kb));
            #pragma unroll
            for (int bb = 0; bb < 2; ++bb)
                LDMX4(bf[bb][0], bf[bb][1], bf[bb][2], bf[bb][3],
                      st + 16384u + swz128(boff[bb] + kb));
            #pragma unroll
            for (int bb = 0; bb < 2; ++bb)
                #pragma unroll
                for (int mt = 0; mt < 2; ++mt) {
                    MMA16816_2(acc[mt][2 * bb],     af[mt], bf[bb][0], bf[bb][1]);
                    MMA16816_2(acc[mt][2 * bb + 1], af[mt], bf[bb][2], bf[bb][3]);
                }
        }
    };

    issue_stage(0, 0);
    issue_stage(1, 1);

    for (int c = 0; c < 16; ++c) {
        if (c < 15) { CPWAIT(1); } else { CPWAIT(0); }
        __syncthreads();
        if (c + 2 < 16) issue_stage(c + 2, (c + 2) % 3);
        compute(c % 3);
    }

    // ---- epilogue
    #pragma unroll
    for (int mt = 0; mt < 2; ++mt) {
        const int m = bm + wm0 + mt * 16 + (lane >> 2);
        #pragma unroll
        for (int nf = 0; nf < 4; ++nf) {
            const int n = bn + wn0 + nf * 8 + (lane & 3) * 2;
            const size_t o0 = oofs + (size_t)m * DMODEL + n;
            const size_t o1 = oofs + (size_t)(m + 8) * DMODEL + n;
            if (EPI == 0) {
                float2 v0 = {acc[mt][nf][0], acc[mt][nf][1]};
                float2 v1 = {acc[mt][nf][2], acc[mt][nf][3]};
                *reinterpret_cast<float2*>(C + o0) = v0;
                *reinterpret_cast<float2*>(C + o1) = v1;
            } else {
                *reinterpret_cast<uint32_t*>(P + o0) = packh(acc[mt][nf][0], acc[mt][nf][1]);
                *reinterpret_cast<uint32_t*>(P + o1) = packh(acc[mt][nf][2], acc[mt][nf][3]);
            }
        }
    }
}

// ---------------------------------------------------------------------------
// fp16 flash attention (round-12 version, unchanged): Q/K/V/P single fp16,
// 2 CTAs/SM, 3-stage cp.async K/V, Q smem-direct.
// ---------------------------------------------------------------------------
static constexpr int RSA    = 72;
static constexpr int QMAT_E = 128 * RSA;
static constexpr int STG_E  = 2 * 64 * RSA;
static constexpr int ASMEM  = (QMAT_E + 3 * STG_E) * 2;   // 73728 bytes

__global__ __launch_bounds__(256, 2)
void attn_mma(const __half* __restrict__ Qh,
              const __half* __restrict__ Kh, const __half* __restrict__ Vh,
              const float* __restrict__ bias,
              __half* __restrict__ AOh)
{
    extern __shared__ __half asmem[];
    const int tid  = threadIdx.x;
    const int lane = tid & 31;
    const int w    = tid >> 5;
    const int qt   = (int)gridDim.x - 1 - (int)blockIdx.x;
    const int h    = blockIdx.y;
    const int b    = blockIdx.z;
    const int q0   = qt * 128;
    const uint32_t sbase = smem_u32(asmem);
    const int nt   = 2 * qt + 2;

    const int krow = tid >> 2;
    const int kseg = (tid & 3) * 32;
    const char* gK = (const char*)(Kh + (size_t)(b * SEQ + krow) * DMODEL + h * DHEAD) + kseg;
    const char* gV = (const char*)(Vh + (size_t)(b * SEQ + krow) * DMODEL + h * DHEAD) + kseg;
    const uint32_t kvoff = (uint32_t)(krow * 144 + kseg);

    auto issue_kv = [&](int kt, int s) {
        const size_t gofs = (size_t)kt * 64 * 2048;
        const uint32_t st = sbase + (uint32_t)(QMAT_E + s * STG_E) * 2;
        CPASYNC16(st + kvoff,              gK + gofs);
        CPASYNC16(st + kvoff + 16,         gK + gofs + 16);
        CPASYNC16(st + 9216u + kvoff,      gV + gofs);
        CPASYNC16(st + 9216u + kvoff + 16, gV + gofs + 16);
        CPCOMMIT();
    };

    issue_kv(0, 0);
    issue_kv(1, 1);

    {
        const __half* Qb = Qh + (size_t)(b * SEQ + q0) * DMODEL + h * DHEAD;
        #pragma unroll
        for (int i = 0; i < 4; ++i) {
            int idx = tid + i * 256;
            int r   = idx >> 3;
            int c16 = idx & 7;
            uint4 v = *reinterpret_cast<const uint4*>(Qb + (size_t)r * DMODEL + c16 * 8);
            *reinterpret_cast<uint4*>(asmem + r * RSA + c16 * 8) = v;
        }
    }
    __syncthreads();

    uint32_t qf[4][4];
    #pragma unroll
    for (int ks = 0; ks < 4; ++ks) {
        const uint32_t off = ((w * 16 + (lane & 15)) * RSA + ks * 16 + ((lane >> 4) << 3)) * 2;
        LDMX4(qf[ks][0], qf[ks][1], qf[ks][2], qf[ks][3], sbase + off);
    }

    float m0 = -1e30f, m1 = -1e30f, l0 = 0.f, l1 = 0.f;
    float o[8][4];
    #pragma unroll
    for (int j = 0; j < 8; ++j)
        #pragma unroll
        for (int q = 0; q < 4; ++q) o[j][q] = 0.f;

    const int q_r0 = q0 + w * 16 + (lane >> 2);
    const int q_r1 = q_r0 + 8;
    const float* bph = bias + (size_t)h * SEQ * SEQ;

    for (int kt = 0; kt < nt; ++kt) {
        const int k0 = kt * 64;
        if (kt + 1 < nt) { CPWAIT(1); } else { CPWAIT(0); }
        __syncthreads();
        if (kt + 2 < nt) issue_kv(kt + 2, (kt + 2) % 3);

        const uint32_t Khu = sbase + (uint32_t)(QMAT_E + (kt % 3) * STG_E) * 2;
        const uint32_t Vhu = Khu + 9216u;

        float sacc[8][4];
        #pragma unroll
        for (int j = 0; j < 8; ++j)
            #pragma unroll
            for (int q = 0; q < 4; ++q) sacc[j][q] = 0.f;
        #pragma unroll
        for (int ks = 0; ks < 4; ++ks) {
            #pragma unroll
            for (int bb = 0; bb < 4; ++bb) {
                const uint32_t off =
                    ((bb * 16 + (lane & 7) + ((lane >> 4) << 3)) * RSA + ks * 16 + (lane & 8)) * 2;
                uint32_t b0, b1, b2, b3;
                LDMX4(b0, b1, b2, b3, Khu + off);
                MMA16816_2(sacc[2 * bb],     qf[ks], b0, b1);
                MMA16816_2(sacc[2 * bb + 1], qf[ks], b2, b3);
            }
        }

        const bool mask = (kt >= 2 * qt);
        const float* r0p = bph + (size_t)q_r0 * SEQ + k0 + 2 * (lane & 3);
        const float* r1p = bph + (size_t)q_r1 * SEQ + k0 + 2 * (lane & 3);
        #pragma unroll
        for (int nf = 0; nf < 8; ++nf) {
            float2 b0 = *reinterpret_cast<const float2*>(r0p + nf * 8);
            float2 b1 = *reinterpret_cast<const float2*>(r1p + nf * 8);
            float v0 = fmaf(sacc[nf][0], 0.18033688f, b0.x * 1.4426950f);
            float v1 = fmaf(sacc[nf][1], 0.18033688f, b0.y * 1.4426950f);
            float v2 = fmaf(sacc[nf][2], 0.18033688f, b1.x * 1.4426950f);
            float v3 = fmaf(sacc[nf][3], 0.18033688f, b1.y * 1.4426950f);
            if (mask) {
                const int kc = k0 + nf * 8 + 2 * (lane & 3);
                if (kc     > q_r0) v0 = -1e30f;
                if (kc + 1 > q_r0) v1 = -1e30f;
                if (kc     > q_r1) v2 = -1e30f;
                if (kc + 1 > q_r1) v3 = -1e30f;
            }
            sacc[nf][0] = v0; sacc[nf][1] = v1; sacc[nf][2] = v2; sacc[nf][3] = v3;
        }

        float m0n = m0, m1n = m1;
        #pragma unroll
        for (int nf = 0; nf < 8; ++nf) {
            m0n = fmaxf(m0n, fmaxf(sacc[nf][0], sacc[nf][1]));
            m1n = fmaxf(m1n, fmaxf(sacc[nf][2], sacc[nf][3]));
        }
        m0n = fmaxf(m0n, __shfl_xor_sync(0xffffffffu, m0n, 1));
        m0n = fmaxf(m0n, __shfl_xor_sync(0xffffffffu, m0n, 2));
        m1n = fmaxf(m1n, __shfl_xor_sync(0xffffffffu, m1n, 1));
        m1n = fmaxf(m1n, __shfl_xor_sync(0xffffffffu, m1n, 2));
        const float c0 = exp2p(m0 - m0n), c1 = exp2p(m1 - m1n);
        m0 = m0n; m1 = m1n;
        l0 *= c0;  l1 *= c1;
        #pragma unroll
        for (int nf = 0; nf < 8; ++nf) {
            o[nf][0] *= c0; o[nf][1] *= c0;
            o[nf][2] *= c1; o[nf][3] *= c1;
        }

        uint32_t pA0[8], pA1[8];
        #pragma unroll
        for (int nf = 0; nf < 8; ++nf) {
            float p0 = exp2p(sacc[nf][0] - m0);
            float p1 = exp2p(sacc[nf][1] - m0);
            float p2 = exp2p(sacc[nf][2] - m1);
            float p3 = exp2p(sacc[nf][3] - m1);
            l0 += p0 + p1; l1 += p2 + p3;
            pA0[nf] = packh(p0, p1);
            pA1[nf] = packh(p2, p3);
        }

        #pragma unroll
        for (int ks = 0; ks < 4; ++ks) {
            uint32_t ah[4] = { pA0[2 * ks], pA1[2 * ks], pA0[2 * ks + 1], pA1[2 * ks + 1] };
            #pragma unroll
            for (int ng = 0; ng < 4; ++ng) {
                const uint32_t off =
                    ((ks * 16 + (lane & 7) + (lane & 8)) * RSA + ng * 16 + ((lane >> 4) << 3)) * 2;
                uint32_t h0, h1, h2, h3;
                LDMX4T(h0, h1, h2, h3, Vhu + off);
                MMA16816_2(o[2 * ng],     ah, h0, h1);
                MMA16816_2(o[2 * ng + 1], ah, h2, h3);
            }
        }
    }

    l0 += __shfl_xor_sync(0xffffffffu, l0, 1);
    l0 += __shfl_xor_sync(0xffffffffu, l0, 2);
    l1 += __shfl_xor_sync(0xffffffffu, l1, 1);
    l1 += __shfl_xor_sync(0xffffffffu, l1, 2);
    const float i0 = 1.f / l0, i1 = 1.f / l1;
    const size_t r0off = (size_t)(b * SEQ + q_r0) * DMODEL + h * DHEAD + 2 * (lane & 3);
    const size_t r1off = (size_t)(b * SEQ + q_r1) * DMODEL + h * DHEAD + 2 * (lane & 3);
    #pragma unroll
    for (int nf = 0; nf < 8; ++nf) {
        *reinterpret_cast<uint32_t*>(AOh + r0off + nf * 8) = packh(o[nf][0] * i0, o[nf][1] * i0);
        *reinterpret_cast<uint32_t*>(AOh + r1off + nf * 8) = packh(o[nf][2] * i1, o[nf][3] * i1);
    }
}

// ---------------------------------------------------------------------------
extern "C" void kernel_launch(void* const* d_in, const int* in_sizes, int n_in,
                              void* d_out, int out_size)
{
    const float* x     = (const float*)d_in[0];
    const float* basis = (const float*)d_in[1];
    const float* sq    = (const float*)d_in[2];
    const float* sk    = (const float*)d_in[3];
    const float* sv    = (const float*)d_in[4];
    const float* so    = (const float*)d_in[5];
    const float* bias  = (const float*)d_in[6];
    float*       out   = (float*)d_out;

    __half *Xh, *BTh, *Bmh, *Bqkv, *BTso, *XBh, *QKV, *AOh, *O1h;
    cudaGetSymbolAddress((void**)&Xh,   g_Xh);
    cudaGetSymbolAddress((void**)&BTh,  g_BTh);
    cudaGetSymbolAddress((void**)&Bmh,  g_Bmh);
    cudaGetSymbolAddress((void**)&Bqkv, g_Bqkv);
    cudaGetSymbolAddress((void**)&BTso, g_BTso);
    cudaGetSymbolAddress((void**)&XBh,  g_XBh);
    cudaGetSymbolAddress((void**)&QKV,  g_QKV);
    cudaGetSymbolAddress((void**)&AOh,  g_AOh);
    cudaGetSymbolAddress((void**)&O1h,  g_O1h);

    const size_t SEG  = (size_t)MROWS * DMODEL;
    const size_t BSEG = (size_t)DMODEL * DMODEL;
    __half* Qh = QKV; __half* Kh = QKV + SEG; __half* Vh = QKV + 2 * SEG;

    cudaFuncSetAttribute(gemm_fp16<0>, cudaFuncAttributeMaxDynamicSharedMemorySize, SMEM_DYN);
    cudaFuncSetAttribute(gemm_fp16<4>, cudaFuncAttributeMaxDynamicSharedMemorySize, SMEM_DYN);
    cudaFuncSetAttribute(attn_mma, cudaFuncAttributeMaxDynamicSharedMemorySize, ASMEM);

    // pre-truncate / pre-scale
    trunc_plain<<<MROWS * DMODEL / 1024, 256>>>((const float4*)x, Xh);
    trunc_plain<<<DMODEL * DMODEL / 1024, 256>>>((const float4*)basis, Bmh);
    trunc_scale3<<<DMODEL * DMODEL / 1024, 256>>>((const float4*)basis,
                                                  (const float4*)sq, (const float4*)sk,
                                                  (const float4*)sv,
                                                  Bqkv, Bqkv + BSEG, Bqkv + 2 * BSEG);
    trans_trunc<<<dim3(32, 32), dim3(32, 8)>>>(basis, BTh, nullptr);
    trans_trunc<<<dim3(32, 32), dim3(32, 8)>>>(basis, BTso, so);

    const dim3 gg(DMODEL / 64, MROWS / 128);
    // G1: XB = X @ basis (plain fp16)
    gemm_fp16<4><<<gg, 256, SMEM_DYN>>>(Xh, BTh, nullptr, XBh, 0, 0);
    // QKV: z-batched over pre-scaled basis copies
    gemm_fp16<4><<<dim3(DMODEL / 64, MROWS / 128, 3), 256, SMEM_DYN>>>(
        XBh, Bqkv, nullptr, QKV, BSEG, SEG);

    attn_mma<<<dim3(SEQ / 128, NHEADS, BATCH), 256, ASMEM>>>(Qh, Kh, Vh, bias, AOh);

    // G5: O1 = AO @ (basis^T · so)
    gemm_fp16<4><<<gg, 256, SMEM_DYN>>>(AOh, BTso, nullptr, O1h, 0, 0);
    // G6: out = O1 @ basis^T (fp32)
    gemm_fp16<0><<<gg, 256, SMEM_DYN>>>(O1h, Bmh, out, nullptr, 0, 0);
}

// round 14
// speedup vs baseline: 1.1720x; 1.1720x over previous
#include <cuda_runtime.h>
#include <cuda_fp16.h>
#include <cstdint>
#include <cstddef>

#define SEQ    2048
#define BATCH  2
#define DMODEL 1024
#define NHEADS 16
#define DHEAD  64
#define MROWS  (BATCH*SEQ)

// ---------------- scratch (device globals; allocation-free rule) ------------
__device__ __half g_Xh [(size_t)MROWS*DMODEL];
__device__ __half g_Bmh[(size_t)DMODEL*DMODEL];            // basis fp16
__device__ __half g_Bs4[(size_t)4*DMODEL*DMODEL];          // basis*sq|sk|sv|so
__device__ __half g_M4 [(size_t)4*DMODEL*DMODEL];          // M_q|M_k|M_v|M_o
__device__ __half g_QKV[(size_t)3*MROWS*DMODEL];           // Q | K | V
__device__ __half g_AOh[(size_t)MROWS*DMODEL];

// ---------------------------------------------------------------------------
__device__ __forceinline__ uint32_t smem_u32(const void* p) {
    uint32_t a;
    asm("{ .reg .u64 t; cvta.to.shared.u64 t, %1; cvt.u32.u64 %0, t; }"
        : "=r"(a) : "l"(p));
    return a;
}

#define LDMX4(r0, r1, r2, r3, addr) \
    asm volatile("ldmatrix.sync.aligned.m8n8.x4.shared.b16 {%0,%1,%2,%3}, [%4];" \
                 : "=r"(r0), "=r"(r1), "=r"(r2), "=r"(r3) : "r"(addr))

#define LDMX4T(r0, r1, r2, r3, addr) \
    asm volatile("ldmatrix.sync.aligned.m8n8.x4.trans.shared.b16 {%0,%1,%2,%3}, [%4];" \
                 : "=r"(r0), "=r"(r1), "=r"(r2), "=r"(r3) : "r"(addr))

#define MMA16816_2(d, a, b0r, b1r) \
    asm volatile("mma.sync.aligned.m16n8k16.row.col.f32.f16.f16.f32 " \
                 "{%0,%1,%2,%3}, {%4,%5,%6,%7}, {%8,%9}, {%0,%1,%2,%3};" \
                 : "+f"((d)[0]), "+f"((d)[1]), "+f"((d)[2]), "+f"((d)[3]) \
                 : "r"((a)[0]), "r"((a)[1]), "r"((a)[2]), "r"((a)[3]), \
                   "r"(b0r), "r"(b1r))

#define CPASYNC16(dst, src) \
    asm volatile("cp.async.cg.shared.global [%0], [%1], 16;" \
                 :: "r"(dst), "l"(src))
#define CPCOMMIT()  asm volatile("cp.async.commit_group;" ::: "memory")
#define CPWAIT(n)   asm volatile("cp.async.wait_group %0;" :: "n"(n) : "memory")

// XOR swizzle for 128B rows: chunk(0..7) ^= row&7 -> conflict-free ldmatrix
__device__ __forceinline__ uint32_t swz128(uint32_t o) {
    return o ^ (((o >> 7) & 7u) << 4);
}

__device__ __forceinline__ uint32_t packh(float a, float b) {
    __half x = __float2half(a), y = __float2half(b);
    return (uint32_t)__half_as_ushort(x) | ((uint32_t)__half_as_ushort(y) << 16);
}

__device__ __forceinline__ void trunc_store(void* hp, float4 v) {
    uint2 hu;
    hu.x = packh(v.x, v.y);
    hu.y = packh(v.z, v.w);
    *reinterpret_cast<uint2*>(hp) = hu;
}

// 2^y via FMA-pipe polynomial (no MUFU)
__device__ __forceinline__ float exp2p(float y) {
    y = fmaxf(y, -120.f);
    float t = y + 12582912.f;
    int   n = (__float_as_int(t) & 0x7FFFFF) - 0x400000;
    float f = y - (t - 12582912.f);
    float p = 1.3333558146e-3f;
    p = fmaf(p, f, 9.6181291076e-3f);
    p = fmaf(p, f, 5.5504108664e-2f);
    p = fmaf(p, f, 2.4022650695e-1f);
    p = fmaf(p, f, 6.9314718056e-1f);
    p = fmaf(p, f, 1.0f);
    return __int_as_float(__float_as_int(p) + (n << 23));
}

// ---------------------------------------------------------------------------
// Pre-truncate / pre-scale helpers
// ---------------------------------------------------------------------------
__global__ void trunc_plain(const float4* __restrict__ in, __half* __restrict__ h) {
    size_t i = (size_t)blockIdx.x * 256 + threadIdx.x;
    trunc_store(h + 4 * i, in[i]);
}

// emit 4 copies of basis with columns (k) scaled by sq/sk/sv/so
__global__ void trunc_scale4(const float4* __restrict__ in,
                             const float4* __restrict__ sq,
                             const float4* __restrict__ sk,
                             const float4* __restrict__ sv,
                             const float4* __restrict__ so,
                             __half* __restrict__ o0, __half* __restrict__ o1,
                             __half* __restrict__ o2, __half* __restrict__ o3) {
    size_t i = (size_t)blockIdx.x * 256 + threadIdx.x;
    const int k4 = (int)(i & 255);
    float4 v = in[i];
    float4 a = sq[k4], b = sk[k4], c = sv[k4], d = so[k4];
    trunc_store(o0 + 4 * i, make_float4(v.x * a.x, v.y * a.y, v.z * a.z, v.w * a.w));
    trunc_store(o1 + 4 * i, make_float4(v.x * b.x, v.y * b.y, v.z * b.z, v.w * b.w));
    trunc_store(o2 + 4 * i, make_float4(v.x * c.x, v.y * c.y, v.z * c.z, v.w * c.w));
    trunc_store(o3 + 4 * i, make_float4(v.x * d.x, v.y * d.y, v.z * d.z, v.w * d.w));
}

// ---------------------------------------------------------------------------
// Single-fp16 mma.sync GEMM (round-12 shape): C[m,n] = sum_k A[m,k]*B[n,k].
// Tile 128x128, BK=64, warp 32x64, 3-stage cp.async, 128B-row swizzle, 2 CTA/SM.
// z-batched via aStride/bStride/oStride.  EPI: 0=fp32 C; 4=fp16 P.
// ---------------------------------------------------------------------------
static constexpr int STAGE_B  = 32768;
static constexpr int SMEM_DYN = 3 * STAGE_B;     // 98304

template<int EPI>
__global__ __launch_bounds__(256, 2)
void gemm_fp16(const __half* __restrict__ A, const __half* __restrict__ Bmat,
               float* __restrict__ C, __half* __restrict__ P,
               size_t aStride, size_t bStride, size_t oStride)
{
    extern __shared__ char smem[];
    const __half* Ap = A    + (size_t)blockIdx.z * aStride;
    const __half* Bp = Bmat + (size_t)blockIdx.z * bStride;
    const size_t oofs = (size_t)blockIdx.z * oStride;

    const int tid  = threadIdx.x;
    const int lane = tid & 31;
    const int wid  = tid >> 5;
    const int bm   = blockIdx.y * 128;
    const int bn   = blockIdx.x * 128;
    const int wm0  = (wid & 3) * 32;
    const int wn0  = (wid >> 2) * 64;
    const uint32_t sbase = smem_u32(smem);

    const int arow = tid >> 1;                  // 0..127
    const int acol = (tid & 1) * 4;             // chunk base 0 or 4

    const char* gA = (const char*)Ap + (size_t)(bm + arow) * 2048 + acol * 16;
    const char* gB = (const char*)Bp + (size_t)(bn + arow) * 2048 + acol * 16;
    uint32_t soA[4];
    #pragma unroll
    for (int i = 0; i < 4; ++i)
        soA[i] = swz128((uint32_t)(arow * 128 + (acol + i) * 16));

    auto issue_stage = [&](int c, int s) {
        const size_t k0b = (size_t)c * 128;
        const uint32_t st = sbase + (uint32_t)s * STAGE_B;
        #pragma unroll
        for (int i = 0; i < 4; ++i)
            CPASYNC16(st + soA[i], gA + k0b + i * 16);
        #pragma unroll
        for (int i = 0; i < 4; ++i)
            CPASYNC16(st + 16384u + soA[i], gB + k0b + i * 16);
        CPCOMMIT();
    };

    float acc[2][8][4];
    #pragma unroll
    for (int i = 0; i < 2; ++i)
        #pragma unroll
        for (int j = 0; j < 8; ++j)
            #pragma unroll
            for (int q = 0; q < 4; ++q) acc[i][j][q] = 0.f;

    uint32_t aoff[2], boff[4];
    #pragma unroll
    for (int mt = 0; mt < 2; ++mt)
        aoff[mt] = (uint32_t)((wm0 + mt * 16 + (lane & 15)) * 128 + ((lane >> 4) << 4));
    #pragma unroll
    for (int bb = 0; bb < 4; ++bb)
        boff[bb] = (uint32_t)((wn0 + bb * 16 + (lane & 7) + ((lane >> 4) << 3)) * 128 + ((lane & 8) << 1));

    auto compute = [&](int s) {
        const uint32_t st = sbase + (uint32_t)s * STAGE_B;
        #pragma unroll
        for (int ks = 0; ks < 4; ++ks) {
            const uint32_t kb = ks * 32u;
            uint32_t af[2][4], bf[4][4];
            #pragma unroll
            for (int mt = 0; mt < 2; ++mt)
                LDMX4(af[mt][0], af[mt][1], af[mt][2], af[mt][3],
                      st + swz128(aoff[mt] + kb));
            #pragma unroll
            for (int bb = 0; bb < 4; ++bb)
                LDMX4(bf[bb][0], bf[bb][1], bf[bb][2], bf[bb][3],
                      st + 16384u + swz128(boff[bb] + kb));
            #pragma unroll
            for (int bb = 0; bb < 4; ++bb)
                #pragma unroll
                for (int mt = 0; mt < 2; ++mt) {
                    MMA16816_2(acc[mt][2 * bb],     af[mt], bf[bb][0], bf[bb][1]);
                    MMA16816_2(acc[mt][2 * bb + 1], af[mt], bf[bb][2], bf[bb][3]);
                }
        }
    };

    issue_stage(0, 0);
    issue_stage(1, 1);

    for (int c = 0; c < 16; ++c) {
        if (c < 15) { CPWAIT(1); } else { CPWAIT(0); }
        __syncthreads();
        if (c + 2 < 16) issue_stage(c + 2, (c + 2) % 3);
        compute(c % 3);
    }

    // ---- epilogue
    #pragma unroll
    for (int mt = 0; mt < 2; ++mt) {
        const int m = bm + wm0 + mt * 16 + (lane >> 2);
        #pragma unroll
        for (int nf = 0; nf < 8; ++nf) {
            const int n = bn + wn0 + nf * 8 + (lane & 3) * 2;
            const size_t o0 = oofs + (size_t)m * DMODEL + n;
            const size_t o1 = oofs + (size_t)(m + 8) * DMODEL + n;
            if (EPI == 0) {
                float2 v0 = {acc[mt][nf][0], acc[mt][nf][1]};
                float2 v1 = {acc[mt][nf][2], acc[mt][nf][3]};
                *reinterpret_cast<float2*>(C + o0) = v0;
                *reinterpret_cast<float2*>(C + o1) = v1;
            } else {
                *reinterpret_cast<uint32_t*>(P + o0) = packh(acc[mt][nf][0], acc[mt][nf][1]);
                *reinterpret_cast<uint32_t*>(P + o1) = packh(acc[mt][nf][2], acc[mt][nf][3]);
            }
        }
    }
}

// ---------------------------------------------------------------------------
// fp16 flash attention (round-12, unchanged): Q/K/V/P single fp16, 2 CTAs/SM,
// 3-stage cp.async K/V, Q smem-direct.
// ---------------------------------------------------------------------------
static constexpr int RSA    = 72;
static constexpr int QMAT_E = 128 * RSA;
static constexpr int STG_E  = 2 * 64 * RSA;
static constexpr int ASMEM  = (QMAT_E + 3 * STG_E) * 2;   // 73728 bytes

__global__ __launch_bounds__(256, 2)
void attn_mma(const __half* __restrict__ Qh,
              const __half* __restrict__ Kh, const __half* __restrict__ Vh,
              const float* __restrict__ bias,
              __half* __restrict__ AOh)
{
    extern __shared__ __half asmem[];
    const int tid  = threadIdx.x;
    const int lane = tid & 31;
    const int w    = tid >> 5;
    const int qt   = (int)gridDim.x - 1 - (int)blockIdx.x;
    const int h    = blockIdx.y;
    const int b    = blockIdx.z;
    const int q0   = qt * 128;
    const uint32_t sbase = smem_u32(asmem);
    const int nt   = 2 * qt + 2;

    const int krow = tid >> 2;
    const int kseg = (tid & 3) * 32;
    const char* gK = (const char*)(Kh + (size_t)(b * SEQ + krow) * DMODEL + h * DHEAD) + kseg;
    const char* gV = (const char*)(Vh + (size_t)(b * SEQ + krow) * DMODEL + h * DHEAD) + kseg;
    const uint32_t kvoff = (uint32_t)(krow * 144 + kseg);

    auto issue_kv = [&](int kt, int s) {
        const size_t gofs = (size_t)kt * 64 * 2048;
        const uint32_t st = sbase + (uint32_t)(QMAT_E + s * STG_E) * 2;
        CPASYNC16(st + kvoff,              gK + gofs);
        CPASYNC16(st + kvoff + 16,         gK + gofs + 16);
        CPASYNC16(st + 9216u + kvoff,      gV + gofs);
        CPASYNC16(st + 9216u + kvoff + 16, gV + gofs + 16);
        CPCOMMIT();
    };

    issue_kv(0, 0);
    issue_kv(1, 1);

    {
        const __half* Qb = Qh + (size_t)(b * SEQ + q0) * DMODEL + h * DHEAD;
        #pragma unroll
        for (int i = 0; i < 4; ++i) {
            int idx = tid + i * 256;
            int r   = idx >> 3;
            int c16 = idx & 7;
            uint4 v = *reinterpret_cast<const uint4*>(Qb + (size_t)r * DMODEL + c16 * 8);
            *reinterpret_cast<uint4*>(asmem + r * RSA + c16 * 8) = v;
        }
    }
    __syncthreads();

    uint32_t qf[4][4];
    #pragma unroll
    for (int ks = 0; ks < 4; ++ks) {
        const uint32_t off = ((w * 16 + (lane & 15)) * RSA + ks * 16 + ((lane >> 4) << 3)) * 2;
        LDMX4(qf[ks][0], qf[ks][1], qf[ks][2], qf[ks][3], sbase + off);
    }

    float m0 = -1e30f, m1 = -1e30f, l0 = 0.f, l1 = 0.f;
    float o[8][4];
    #pragma unroll
    for (int j = 0; j < 8; ++j)
        #pragma unroll
        for (int q = 0; q < 4; ++q) o[j][q] = 0.f;

    const int q_r0 = q0 + w * 16 + (lane >> 2);
    const int q_r1 = q_r0 + 8;
    const float* bph = bias + (size_t)h * SEQ * SEQ;

    for (int kt = 0; kt < nt; ++kt) {
        const int k0 = kt * 64;
        if (kt + 1 < nt) { CPWAIT(1); } else { CPWAIT(0); }
        __syncthreads();
        if (kt + 2 < nt) issue_kv(kt + 2, (kt + 2) % 3);

        const uint32_t Khu = sbase + (uint32_t)(QMAT_E + (kt % 3) * STG_E) * 2;
        const uint32_t Vhu = Khu + 9216u;

        float sacc[8][4];
        #pragma unroll
        for (int j = 0; j < 8; ++j)
            #pragma unroll
            for (int q = 0; q < 4; ++q) sacc[j][q] = 0.f;
        #pragma unroll
        for (int ks = 0; ks < 4; ++ks) {
            #pragma unroll
            for (int bb = 0; bb < 4; ++bb) {
                const uint32_t off =
                    ((bb * 16 + (lane & 7) + ((lane >> 4) << 3)) * RSA + ks * 16 + (lane & 8)) * 2;
                uint32_t b0, b1, b2, b3;
                LDMX4(b0, b1, b2, b3, Khu + off);
                MMA16816_2(sacc[2 * bb],     qf[ks], b0, b1);
                MMA16816_2(sacc[2 * bb + 1], qf[ks], b2, b3);
            }
        }

        const bool mask = (kt >= 2 * qt);
        const float* r0p = bph + (size_t)q_r0 * SEQ + k0 + 2 * (lane & 3);
        const float* r1p = bph + (size_t)q_r1 * SEQ + k0 + 2 * (lane & 3);
        #pragma unroll
        for (int nf = 0; nf < 8; ++nf) {
            float2 b0 = *reinterpret_cast<const float2*>(r0p + nf * 8);
            float2 b1 = *reinterpret_cast<const float2*>(r1p + nf * 8);
            float v0 = fmaf(sacc[nf][0], 0.18033688f, b0.x * 1.4426950f);
            float v1 = fmaf(sacc[nf][1], 0.18033688f, b0.y * 1.4426950f);
            float v2 = fmaf(sacc[nf][2], 0.18033688f, b1.x * 1.4426950f);
            float v3 = fmaf(sacc[nf][3], 0.18033688f, b1.y * 1.4426950f);
            if (mask) {
                const int kc = k0 + nf * 8 + 2 * (lane & 3);
                if (kc     > q_r0) v0 = -1e30f;
                if (kc + 1 > q_r0) v1 = -1e30f;
                if (kc     > q_r1) v2 = -1e30f;
                if (kc + 1 > q_r1) v3 = -1e30f;
            }
            sacc[nf][0] = v0; sacc[nf][1] = v1; sacc[nf][2] = v2; sacc[nf][3] = v3;
        }

        float m0n = m0, m1n = m1;
        #pragma unroll
        for (int nf = 0; nf < 8; ++nf) {
            m0n = fmaxf(m0n, fmaxf(sacc[nf][0], sacc[nf][1]));
            m1n = fmaxf(m1n, fmaxf(sacc[nf][2], sacc[nf][3]));
        }
        m0n = fmaxf(m0n, __shfl_xor_sync(0xffffffffu, m0n, 1));
        m0n = fmaxf(m0n, __shfl_xor_sync(0xffffffffu, m0n, 2));
        m1n = fmaxf(m1n, __shfl_xor_sync(0xffffffffu, m1n, 1));
        m1n = fmaxf(m1n, __shfl_xor_sync(0xffffffffu, m1n, 2));
        const float c0 = exp2p(m0 - m0n), c1 = exp2p(m1 - m1n);
        m0 = m0n; m1 = m1n;
        l0 *= c0;  l1 *= c1;
        #pragma unroll
        for (int nf = 0; nf < 8; ++nf) {
            o[nf][0] *= c0; o[nf][1] *= c0;
            o[nf][2] *= c1; o[nf][3] *= c1;
        }

        uint32_t pA0[8], pA1[8];
        #pragma unroll
        for (int nf = 0; nf < 8; ++nf) {
            float p0 = exp2p(sacc[nf][0] - m0);
            float p1 = exp2p(sacc[nf][1] - m0);
            float p2 = exp2p(sacc[nf][2] - m1);
            float p3 = exp2p(sacc[nf][3] - m1);
            l0 += p0 + p1; l1 += p2 + p3;
            pA0[nf] = packh(p0, p1);
            pA1[nf] = packh(p2, p3);
        }

        #pragma unroll
        for (int ks = 0; ks < 4; ++ks) {
            uint32_t ah[4] = { pA0[2 * ks], pA1[2 * ks], pA0[2 * ks + 1], pA1[2 * ks + 1] };
            #pragma unroll
            for (int ng = 0; ng < 4; ++ng) {
                const uint32_t off =
                    ((ks * 16 + (lane & 7) + (lane & 8)) * RSA + ng * 16 + ((lane >> 4) << 3)) * 2;
                uint32_t h0, h1, h2, h3;
                LDMX4T(h0, h1, h2, h3, Vhu + off);
                MMA16816_2(o[2 * ng],     ah, h0, h1);
                MMA16816_2(o[2 * ng + 1], ah, h2, h3);
            }
        }
    }

    l0 += __shfl_xor_sync(0xffffffffu, l0, 1);
    l0 += __shfl_xor_sync(0xffffffffu, l0, 2);
    l1 += __shfl_xor_sync(0xffffffffu, l1, 1);
    l1 += __shfl_xor_sync(0xffffffffu, l1, 2);
    const float i0 = 1.f / l0, i1 = 1.f / l1;
    const size_t r0off = (size_t)(b * SEQ + q_r0) * DMODEL + h * DHEAD + 2 * (lane & 3);
    const size_t r1off = (size_t)(b * SEQ + q_r1) * DMODEL + h * DHEAD + 2 * (lane & 3);
    #pragma unroll
    for (int nf = 0; nf < 8; ++nf) {
        *reinterpret_cast<uint32_t*>(AOh + r0off + nf * 8) = packh(o[nf][0] * i0, o[nf][1] * i0);
        *reinterpret_cast<uint32_t*>(AOh + r1off + nf * 8) = packh(o[nf][2] * i1, o[nf][3] * i1);
    }
}

// ---------------------------------------------------------------------------
extern "C" void kernel_launch(void* const* d_in, const int* in_sizes, int n_in,
                              void* d_out, int out_size)
{
    const float* x     = (const float*)d_in[0];
    const float* basis = (const float*)d_in[1];
    const float* sq    = (const float*)d_in[2];
    const float* sk    = (const float*)d_in[3];
    const float* sv    = (const float*)d_in[4];
    const float* so    = (const float*)d_in[5];
    const float* bias  = (const float*)d_in[6];
    float*       out   = (float*)d_out;

    __half *Xh, *Bmh, *Bs4, *M4, *QKV, *AOh;
    cudaGetSymbolAddress((void**)&Xh,  g_Xh);
    cudaGetSymbolAddress((void**)&Bmh, g_Bmh);
    cudaGetSymbolAddress((void**)&Bs4, g_Bs4);
    cudaGetSymbolAddress((void**)&M4,  g_M4);
    cudaGetSymbolAddress((void**)&QKV, g_QKV);
    cudaGetSymbolAddress((void**)&AOh, g_AOh);

    const size_t SEG  = (size_t)MROWS * DMODEL;
    const size_t BSEG = (size_t)DMODEL * DMODEL;
    __half* Qh = QKV; __half* Kh = QKV + SEG; __half* Vh = QKV + 2 * SEG;
    __half* Mo = M4 + 3 * BSEG;

    cudaFuncSetAttribute(gemm_fp16<0>, cudaFuncAttributeMaxDynamicSharedMemorySize, SMEM_DYN);
    cudaFuncSetAttribute(gemm_fp16<4>, cudaFuncAttributeMaxDynamicSharedMemorySize, SMEM_DYN);
    cudaFuncSetAttribute(attn_mma, cudaFuncAttributeMaxDynamicSharedMemorySize, ASMEM);

    // pre-truncate / pre-scale
    trunc_plain<<<MROWS * DMODEL / 1024, 256>>>((const float4*)x, Xh);
    trunc_plain<<<DMODEL * DMODEL / 1024, 256>>>((const float4*)basis, Bmh);
    trunc_scale4<<<DMODEL * DMODEL / 1024, 256>>>((const float4*)basis,
                                                  (const float4*)sq, (const float4*)sk,
                                                  (const float4*)sv, (const float4*)so,
                                                  Bs4, Bs4 + BSEG, Bs4 + 2 * BSEG, Bs4 + 3 * BSEG);

    // M-build: M_s = (basis*s) @ basis^T, symmetric; all 4 in one z-batched launch
    gemm_fp16<4><<<dim3(DMODEL / 128, DMODEL / 128, 4), 256, SMEM_DYN>>>(
        Bs4, Bmh, nullptr, M4, BSEG, 0, BSEG);

    // QKV = X @ M_{q,k,v} (M symmetric -> row-major is K-major form)
    gemm_fp16<4><<<dim3(DMODEL / 128, MROWS / 128, 3), 256, SMEM_DYN>>>(
        Xh, M4, nullptr, QKV, 0, BSEG, SEG);

    attn_mma<<<dim3(SEQ / 128, NHEADS, BATCH), 256, ASMEM>>>(Qh, Kh, Vh, bias, AOh);

    // out = AO @ M_o (fp32 epilogue)
    gemm_fp16<0><<<dim3(DMODEL / 128, MROWS / 128), 256, SMEM_DYN>>>(
        AOh, Mo, out, nullptr, 0, 0, 0);
}

// round 15
// speedup vs baseline: 1.2070x; 1.0299x over previous
#include <cuda_runtime.h>
#include <cuda_fp16.h>
#include <cstdint>
#include <cstddef>

#define SEQ    2048
#define BATCH  2
#define DMODEL 1024
#define NHEADS 16
#define DHEAD  64
#define MROWS  (BATCH*SEQ)

// ---------------- scratch (device globals; allocation-free rule) ------------
__device__ __half g_Xh [(size_t)MROWS*DMODEL];
__device__ __half g_Bmh[(size_t)DMODEL*DMODEL];            // basis fp16
__device__ __half g_Bs4[(size_t)4*DMODEL*DMODEL];          // basis*sq|sk|sv|so
__device__ __half g_M4 [(size_t)4*DMODEL*DMODEL];          // M_q|M_k|M_v|M_o
__device__ __half g_QKV[(size_t)3*MROWS*DMODEL];           // Q | K | V
__device__ __half g_AOh[(size_t)MROWS*DMODEL];

// ---------------------------------------------------------------------------
__device__ __forceinline__ uint32_t smem_u32(const void* p) {
    uint32_t a;
    asm("{ .reg .u64 t; cvta.to.shared.u64 t, %1; cvt.u32.u64 %0, t; }"
        : "=r"(a) : "l"(p));
    return a;
}

#define LDMX4(r0, r1, r2, r3, addr) \
    asm volatile("ldmatrix.sync.aligned.m8n8.x4.shared.b16 {%0,%1,%2,%3}, [%4];" \
                 : "=r"(r0), "=r"(r1), "=r"(r2), "=r"(r3) : "r"(addr))

#define LDMX4T(r0, r1, r2, r3, addr) \
    asm volatile("ldmatrix.sync.aligned.m8n8.x4.trans.shared.b16 {%0,%1,%2,%3}, [%4];" \
                 : "=r"(r0), "=r"(r1), "=r"(r2), "=r"(r3) : "r"(addr))

#define MMA16816_2(d, a, b0r, b1r) \
    asm volatile("mma.sync.aligned.m16n8k16.row.col.f32.f16.f16.f32 " \
                 "{%0,%1,%2,%3}, {%4,%5,%6,%7}, {%8,%9}, {%0,%1,%2,%3};" \
                 : "+f"((d)[0]), "+f"((d)[1]), "+f"((d)[2]), "+f"((d)[3]) \
                 : "r"((a)[0]), "r"((a)[1]), "r"((a)[2]), "r"((a)[3]), \
                   "r"(b0r), "r"(b1r))

#define CPASYNC16(dst, src) \
    asm volatile("cp.async.cg.shared.global [%0], [%1], 16;" \
                 :: "r"(dst), "l"(src))
#define CPCOMMIT()  asm volatile("cp.async.commit_group;" ::: "memory")
#define CPWAIT(n)   asm volatile("cp.async.wait_group %0;" :: "n"(n) : "memory")

// XOR swizzle for 128B rows: chunk(0..7) ^= row&7 -> conflict-free ldmatrix
__device__ __forceinline__ uint32_t swz128(uint32_t o) {
    return o ^ (((o >> 7) & 7u) << 4);
}

__device__ __forceinline__ uint32_t packh(float a, float b) {
    __half x = __float2half(a), y = __float2half(b);
    return (uint32_t)__half_as_ushort(x) | ((uint32_t)__half_as_ushort(y) << 16);
}

__device__ __forceinline__ void trunc_store(void* hp, float4 v) {
    uint2 hu;
    hu.x = packh(v.x, v.y);
    hu.y = packh(v.z, v.w);
    *reinterpret_cast<uint2*>(hp) = hu;
}

// 2^y on the MUFU pipe (EX2) — frees the FMA pipe in the attention hot loop.
__device__ __forceinline__ float exp2m(float y) {
    float r;
    asm("ex2.approx.ftz.f32 %0, %1;" : "=f"(r) : "f"(y));
    return r;
}

// ---------------------------------------------------------------------------
// Pre-truncate / pre-scale helpers
// ---------------------------------------------------------------------------
__global__ void trunc_plain(const float4* __restrict__ in, __half* __restrict__ h) {
    size_t i = (size_t)blockIdx.x * 256 + threadIdx.x;
    trunc_store(h + 4 * i, in[i]);
}

// emit 4 copies of basis with columns (k) scaled by sq/sk/sv/so
__global__ void trunc_scale4(const float4* __restrict__ in,
                             const float4* __restrict__ sq,
                             const float4* __restrict__ sk,
                             const float4* __restrict__ sv,
                             const float4* __restrict__ so,
                             __half* __restrict__ o0, __half* __restrict__ o1,
                             __half* __restrict__ o2, __half* __restrict__ o3) {
    size_t i = (size_t)blockIdx.x * 256 + threadIdx.x;
    const int k4 = (int)(i & 255);
    float4 v = in[i];
    float4 a = sq[k4], b = sk[k4], c = sv[k4], d = so[k4];
    trunc_store(o0 + 4 * i, make_float4(v.x * a.x, v.y * a.y, v.z * a.z, v.w * a.w));
    trunc_store(o1 + 4 * i, make_float4(v.x * b.x, v.y * b.y, v.z * b.z, v.w * b.w));
    trunc_store(o2 + 4 * i, make_float4(v.x * c.x, v.y * c.y, v.z * c.z, v.w * c.w));
    trunc_store(o3 + 4 * i, make_float4(v.x * d.x, v.y * d.y, v.z * d.z, v.w * d.w));
}

// ---------------------------------------------------------------------------
// Single-fp16 mma.sync GEMM: C[m,n] = sum_k A[m,k]*B[n,k].
// Tile 128x128, BK=64, warp 32x64, 3-stage cp.async, 128B-row swizzle, 2 CTA/SM.
// z-batched via aStride/bStride/oStride.  EPI: 0=fp32 C; 4=fp16 P.
// ---------------------------------------------------------------------------
static constexpr int STAGE_B  = 32768;
static constexpr int SMEM_DYN = 3 * STAGE_B;     // 98304

template<int EPI>
__global__ __launch_bounds__(256, 2)
void gemm_fp16(const __half* __restrict__ A, const __half* __restrict__ Bmat,
               float* __restrict__ C, __half* __restrict__ P,
               size_t aStride, size_t bStride, size_t oStride)
{
    extern __shared__ char smem[];
    const __half* Ap = A    + (size_t)blockIdx.z * aStride;
    const __half* Bp = Bmat + (size_t)blockIdx.z * bStride;
    const size_t oofs = (size_t)blockIdx.z * oStride;

    const int tid  = threadIdx.x;
    const int lane = tid & 31;
    const int wid  = tid >> 5;
    const int bm   = blockIdx.y * 128;
    const int bn   = blockIdx.x * 128;
    const int wm0  = (wid & 3) * 32;
    const int wn0  = (wid >> 2) * 64;
    const uint32_t sbase = smem_u32(smem);

    const int arow = tid >> 1;                  // 0..127
    const int acol = (tid & 1) * 4;             // chunk base 0 or 4

    const char* gA = (const char*)Ap + (size_t)(bm + arow) * 2048 + acol * 16;
    const char* gB = (const char*)Bp + (size_t)(bn + arow) * 2048 + acol * 16;
    uint32_t soA[4];
    #pragma unroll
    for (int i = 0; i < 4; ++i)
        soA[i] = swz128((uint32_t)(arow * 128 + (acol + i) * 16));

    auto issue_stage = [&](int c, int s) {
        const size_t k0b = (size_t)c * 128;
        const uint32_t st = sbase + (uint32_t)s * STAGE_B;
        #pragma unroll
        for (int i = 0; i < 4; ++i)
            CPASYNC16(st + soA[i], gA + k0b + i * 16);
        #pragma unroll
        for (int i = 0; i < 4; ++i)
            CPASYNC16(st + 16384u + soA[i], gB + k0b + i * 16);
        CPCOMMIT();
    };

    float acc[2][8][4];
    #pragma unroll
    for (int i = 0; i < 2; ++i)
        #pragma unroll
        for (int j = 0; j < 8; ++j)
            #pragma unroll
            for (int q = 0; q < 4; ++q) acc[i][j][q] = 0.f;

    uint32_t aoff[2], boff[4];
    #pragma unroll
    for (int mt = 0; mt < 2; ++mt)
        aoff[mt] = (uint32_t)((wm0 + mt * 16 + (lane & 15)) * 128 + ((lane >> 4) << 4));
    #pragma unroll
    for (int bb = 0; bb < 4; ++bb)
        boff[bb] = (uint32_t)((wn0 + bb * 16 + (lane & 7) + ((lane >> 4) << 3)) * 128 + ((lane & 8) << 1));

    auto compute = [&](int s) {
        const uint32_t st = sbase + (uint32_t)s * STAGE_B;
        #pragma unroll
        for (int ks = 0; ks < 4; ++ks) {
            const uint32_t kb = ks * 32u;
            uint32_t af[2][4], bf[4][4];
            #pragma unroll
            for (int mt = 0; mt < 2; ++mt)
                LDMX4(af[mt][0], af[mt][1], af[mt][2], af[mt][3],
                      st + swz128(aoff[mt] + kb));
            #pragma unroll
            for (int bb = 0; bb < 4; ++bb)
                LDMX4(bf[bb][0], bf[bb][1], bf[bb][2], bf[bb][3],
                      st + 16384u + swz128(boff[bb] + kb));
            #pragma unroll
            for (int bb = 0; bb < 4; ++bb)
                #pragma unroll
                for (int mt = 0; mt < 2; ++mt) {
                    MMA16816_2(acc[mt][2 * bb],     af[mt], bf[bb][0], bf[bb][1]);
                    MMA16816_2(acc[mt][2 * bb + 1], af[mt], bf[bb][2], bf[bb][3]);
                }
        }
    };

    issue_stage(0, 0);
    issue_stage(1, 1);

    for (int c = 0; c < 16; ++c) {
        if (c < 15) { CPWAIT(1); } else { CPWAIT(0); }
        __syncthreads();
        if (c + 2 < 16) issue_stage(c + 2, (c + 2) % 3);
        compute(c % 3);
    }

    // ---- epilogue
    #pragma unroll
    for (int mt = 0; mt < 2; ++mt) {
        const int m = bm + wm0 + mt * 16 + (lane >> 2);
        #pragma unroll
        for (int nf = 0; nf < 8; ++nf) {
            const int n = bn + wn0 + nf * 8 + (lane & 3) * 2;
            const size_t o0 = oofs + (size_t)m * DMODEL + n;
            const size_t o1 = oofs + (size_t)(m + 8) * DMODEL + n;
            if (EPI == 0) {
                float2 v0 = {acc[mt][nf][0], acc[mt][nf][1]};
                float2 v1 = {acc[mt][nf][2], acc[mt][nf][3]};
                *reinterpret_cast<float2*>(C + o0) = v0;
                *reinterpret_cast<float2*>(C + o1) = v1;
            } else {
                *reinterpret_cast<uint32_t*>(P + o0) = packh(acc[mt][nf][0], acc[mt][nf][1]);
                *reinterpret_cast<uint32_t*>(P + o1) = packh(acc[mt][nf][2], acc[mt][nf][3]);
            }
        }
    }
}

// ---------------------------------------------------------------------------
// fp16 flash attention: Q/K/V/P single fp16, 2 CTAs/SM, 3-stage cp.async K/V,
// Q smem-direct. Softmax exp on MUFU (ex2.approx) — FMA pipe stays free.
// ---------------------------------------------------------------------------
static constexpr int RSA    = 72;
static constexpr int QMAT_E = 128 * RSA;
static constexpr int STG_E  = 2 * 64 * RSA;
static constexpr int ASMEM  = (QMAT_E + 3 * STG_E) * 2;   // 73728 bytes

__global__ __launch_bounds__(256, 2)
void attn_mma(const __half* __restrict__ Qh,
              const __half* __restrict__ Kh, const __half* __restrict__ Vh,
              const float* __restrict__ bias,
              __half* __restrict__ AOh)
{
    extern __shared__ __half asmem[];
    const int tid  = threadIdx.x;
    const int lane = tid & 31;
    const int w    = tid >> 5;
    const int qt   = (int)gridDim.x - 1 - (int)blockIdx.x;
    const int h    = blockIdx.y;
    const int b    = blockIdx.z;
    const int q0   = qt * 128;
    const uint32_t sbase = smem_u32(asmem);
    const int nt   = 2 * qt + 2;

    const int krow = tid >> 2;
    const int kseg = (tid & 3) * 32;
    const char* gK = (const char*)(Kh + (size_t)(b * SEQ + krow) * DMODEL + h * DHEAD) + kseg;
    const char* gV = (const char*)(Vh + (size_t)(b * SEQ + krow) * DMODEL + h * DHEAD) + kseg;
    const uint32_t kvoff = (uint32_t)(krow * 144 + kseg);

    auto issue_kv = [&](int kt, int s) {
        const size_t gofs = (size_t)kt * 64 * 2048;
        const uint32_t st = sbase + (uint32_t)(QMAT_E + s * STG_E) * 2;
        CPASYNC16(st + kvoff,              gK + gofs);
        CPASYNC16(st + kvoff + 16,         gK + gofs + 16);
        CPASYNC16(st + 9216u + kvoff,      gV + gofs);
        CPASYNC16(st + 9216u + kvoff + 16, gV + gofs + 16);
        CPCOMMIT();
    };

    issue_kv(0, 0);
    issue_kv(1, 1);

    {
        const __half* Qb = Qh + (size_t)(b * SEQ + q0) * DMODEL + h * DHEAD;
        #pragma unroll
        for (int i = 0; i < 4; ++i) {
            int idx = tid + i * 256;
            int r   = idx >> 3;
            int c16 = idx & 7;
            uint4 v = *reinterpret_cast<const uint4*>(Qb + (size_t)r * DMODEL + c16 * 8);
            *reinterpret_cast<uint4*>(asmem + r * RSA + c16 * 8) = v;
        }
    }
    __syncthreads();

    uint32_t qf[4][4];
    #pragma unroll
    for (int ks = 0; ks < 4; ++ks) {
        const uint32_t off = ((w * 16 + (lane & 15)) * RSA + ks * 16 + ((lane >> 4) << 3)) * 2;
        LDMX4(qf[ks][0], qf[ks][1], qf[ks][2], qf[ks][3], sbase + off);
    }

    float m0 = -1e30f, m1 = -1e30f, l0 = 0.f, l1 = 0.f;
    float o[8][4];
    #pragma unroll
    for (int j = 0; j < 8; ++j)
        #pragma unroll
        for (int q = 0; q < 4; ++q) o[j][q] = 0.f;

    const int q_r0 = q0 + w * 16 + (lane >> 2);
    const int q_r1 = q_r0 + 8;
    const float* bph = bias + (size_t)h * SEQ * SEQ;

    for (int kt = 0; kt < nt; ++kt) {
        const int k0 = kt * 64;
        if (kt + 1 < nt) { CPWAIT(1); } else { CPWAIT(0); }
        __syncthreads();
        if (kt + 2 < nt) issue_kv(kt + 2, (kt + 2) % 3);

        const uint32_t Khu = sbase + (uint32_t)(QMAT_E + (kt % 3) * STG_E) * 2;
        const uint32_t Vhu = Khu + 9216u;

        float sacc[8][4];
        #pragma unroll
        for (int j = 0; j < 8; ++j)
            #pragma unroll
            for (int q = 0; q < 4; ++q) sacc[j][q] = 0.f;
        #pragma unroll
        for (int ks = 0; ks < 4; ++ks) {
            #pragma unroll
            for (int bb = 0; bb < 4; ++bb) {
                const uint32_t off =
                    ((bb * 16 + (lane & 7) + ((lane >> 4) << 3)) * RSA + ks * 16 + (lane & 8)) * 2;
                uint32_t b0, b1, b2, b3;
                LDMX4(b0, b1, b2, b3, Khu + off);
                MMA16816_2(sacc[2 * bb],     qf[ks], b0, b1);
                MMA16816_2(sacc[2 * bb + 1], qf[ks], b2, b3);
            }
        }

        const bool mask = (kt >= 2 * qt);
        const float* r0p = bph + (size_t)q_r0 * SEQ + k0 + 2 * (lane & 3);
        const float* r1p = bph + (size_t)q_r1 * SEQ + k0 + 2 * (lane & 3);
        #pragma unroll
        for (int nf = 0; nf < 8; ++nf) {
            float2 b0 = *reinterpret_cast<const float2*>(r0p + nf * 8);
            float2 b1 = *reinterpret_cast<const float2*>(r1p + nf * 8);
            float v0 = fmaf(sacc[nf][0], 0.18033688f, b0.x * 1.4426950f);
            float v1 = fmaf(sacc[nf][1], 0.18033688f, b0.y * 1.4426950f);
            float v2 = fmaf(sacc[nf][2], 0.18033688f, b1.x * 1.4426950f);
            float v3 = fmaf(sacc[nf][3], 0.18033688f, b1.y * 1.4426950f);
            if (mask) {
                const int kc = k0 + nf * 8 + 2 * (lane & 3);
                if (kc     > q_r0) v0 = -1e30f;
                if (kc + 1 > q_r0) v1 = -1e30f;
                if (kc     > q_r1) v2 = -1e30f;
                if (kc + 1 > q_r1) v3 = -1e30f;
            }
            sacc[nf][0] = v0; sacc[nf][1] = v1; sacc[nf][2] = v2; sacc[nf][3] = v3;
        }

        float m0n = m0, m1n = m1;
        #pragma unroll
        for (int nf = 0; nf < 8; ++nf) {
            m0n = fmaxf(m0n, fmaxf(sacc[nf][0], sacc[nf][1]));
            m1n = fmaxf(m1n, fmaxf(sacc[nf][2], sacc[nf][3]));
        }
        m0n = fmaxf(m0n, __shfl_xor_sync(0xffffffffu, m0n, 1));
        m0n = fmaxf(m0n, __shfl_xor_sync(0xffffffffu, m0n, 2));
        m1n = fmaxf(m1n, __shfl_xor_sync(0xffffffffu, m1n, 1));
        m1n = fmaxf(m1n, __shfl_xor_sync(0xffffffffu, m1n, 2));
        const float c0 = exp2m(m0 - m0n), c1 = exp2m(m1 - m1n);
        m0 = m0n; m1 = m1n;
        l0 *= c0;  l1 *= c1;
        #pragma unroll
        for (int nf = 0; nf < 8; ++nf) {
            o[nf][0] *= c0; o[nf][1] *= c0;
            o[nf][2] *= c1; o[nf][3] *= c1;
        }

        uint32_t pA0[8], pA1[8];
        #pragma unroll
        for (int nf = 0; nf < 8; ++nf) {
            float p0 = exp2m(sacc[nf][0] - m0);
            float p1 = exp2m(sacc[nf][1] - m0);
            float p2 = exp2m(sacc[nf][2] - m1);
            float p3 = exp2m(sacc[nf][3] - m1);
            l0 += p0 + p1; l1 += p2 + p3;
            pA0[nf] = packh(p0, p1);
            pA1[nf] = packh(p2, p3);
        }

        #pragma unroll
        for (int ks = 0; ks < 4; ++ks) {
            uint32_t ah[4] = { pA0[2 * ks], pA1[2 * ks], pA0[2 * ks + 1], pA1[2 * ks + 1] };
            #pragma unroll
            for (int ng = 0; ng < 4; ++ng) {
                const uint32_t off =
                    ((ks * 16 + (lane & 7) + (lane & 8)) * RSA + ng * 16 + ((lane >> 4) << 3)) * 2;
                uint32_t h0, h1, h2, h3;
                LDMX4T(h0, h1, h2, h3, Vhu + off);
                MMA16816_2(o[2 * ng],     ah, h0, h1);
                MMA16816_2(o[2 * ng + 1], ah, h2, h3);
            }
        }
    }

    l0 += __shfl_xor_sync(0xffffffffu, l0, 1);
    l0 += __shfl_xor_sync(0xffffffffu, l0, 2);
    l1 += __shfl_xor_sync(0xffffffffu, l1, 1);
    l1 += __shfl_xor_sync(0xffffffffu, l1, 2);
    const float i0 = 1.f / l0, i1 = 1.f / l1;
    const size_t r0off = (size_t)(b * SEQ + q_r0) * DMODEL + h * DHEAD + 2 * (lane & 3);
    const size_t r1off = (size_t)(b * SEQ + q_r1) * DMODEL + h * DHEAD + 2 * (lane & 3);
    #pragma unroll
    for (int nf = 0; nf < 8; ++nf) {
        *reinterpret_cast<uint32_t*>(AOh + r0off + nf * 8) = packh(o[nf][0] * i0, o[nf][1] * i0);
        *reinterpret_cast<uint32_t*>(AOh + r1off + nf * 8) = packh(o[nf][2] * i1, o[nf][3] * i1);
    }
}

// ---------------------------------------------------------------------------
extern "C" void kernel_launch(void* const* d_in, const int* in_sizes, int n_in,
                              void* d_out, int out_size)
{
    const float* x     = (const float*)d_in[0];
    const float* basis = (const float*)d_in[1];
    const float* sq    = (const float*)d_in[2];
    const float* sk    = (const float*)d_in[3];
    const float* sv    = (const float*)d_in[4];
    const float* so    = (const float*)d_in[5];
    const float* bias  = (const float*)d_in[6];
    float*       out   = (float*)d_out;

    __half *Xh, *Bmh, *Bs4, *M4, *QKV, *AOh;
    cudaGetSymbolAddress((void**)&Xh,  g_Xh);
    cudaGetSymbolAddress((void**)&Bmh, g_Bmh);
    cudaGetSymbolAddress((void**)&Bs4, g_Bs4);
    cudaGetSymbolAddress((void**)&M4,  g_M4);
    cudaGetSymbolAddress((void**)&QKV, g_QKV);
    cudaGetSymbolAddress((void**)&AOh, g_AOh);

    const size_t SEG  = (size_t)MROWS * DMODEL;
    const size_t BSEG = (size_t)DMODEL * DMODEL;
    __half* Qh = QKV; __half* Kh = QKV + SEG; __half* Vh = QKV + 2 * SEG;
    __half* Mo = M4 + 3 * BSEG;

    cudaFuncSetAttribute(gemm_fp16<0>, cudaFuncAttributeMaxDynamicSharedMemorySize, SMEM_DYN);
    cudaFuncSetAttribute(gemm_fp16<4>, cudaFuncAttributeMaxDynamicSharedMemorySize, SMEM_DYN);
    cudaFuncSetAttribute(attn_mma, cudaFuncAttributeMaxDynamicSharedMemorySize, ASMEM);

    // pre-truncate / pre-scale
    trunc_plain<<<MROWS * DMODEL / 1024, 256>>>((const float4*)x, Xh);
    trunc_plain<<<DMODEL * DMODEL / 1024, 256>>>((const float4*)basis, Bmh);
    trunc_scale4<<<DMODEL * DMODEL / 1024, 256>>>((const float4*)basis,
                                                  (const float4*)sq, (const float4*)sk,
                                                  (const float4*)sv, (const float4*)so,
                                                  Bs4, Bs4 + BSEG, Bs4 + 2 * BSEG, Bs4 + 3 * BSEG);

    // M-build: M_s = (basis*s) @ basis^T, symmetric; all 4 in one z-batched launch
    gemm_fp16<4><<<dim3(DMODEL / 128, DMODEL / 128, 4), 256, SMEM_DYN>>>(
        Bs4, Bmh, nullptr, M4, BSEG, 0, BSEG);

    // QKV = X @ M_{q,k,v}
    gemm_fp16<4><<<dim3(DMODEL / 128, MROWS / 128, 3), 256, SMEM_DYN>>>(
        Xh, M4, nullptr, QKV, 0, BSEG, SEG);

    attn_mma<<<dim3(SEQ / 128, NHEADS, BATCH), 256, ASMEM>>>(Qh, Kh, Vh, bias, AOh);

    // out = AO @ M_o (fp32 epilogue)
    gemm_fp16<0><<<dim3(DMODEL / 128, MROWS / 128), 256, SMEM_DYN>>>(
        AOh, Mo, out, nullptr, 0, 0, 0);
}

// round 16
// speedup vs baseline: 1.2218x; 1.0123x over previous
#include <cuda_runtime.h>
#include <cuda_fp16.h>
#include <cstdint>
#include <cstddef>

#define SEQ    2048
#define BATCH  2
#define DMODEL 1024
#define NHEADS 16
#define DHEAD  64
#define MROWS  (BATCH*SEQ)

// ---------------- scratch (device globals; allocation-free rule) ------------
__device__ __half g_Xh [(size_t)MROWS*DMODEL];
__device__ __half g_Bmh[(size_t)DMODEL*DMODEL];            // basis fp16
__device__ __half g_Bs4[(size_t)4*DMODEL*DMODEL];          // basis*sq|sk|sv|so
__device__ __half g_M4 [(size_t)4*DMODEL*DMODEL];          // M_q|M_k|M_v|M_o
__device__ __half g_QKV[(size_t)3*MROWS*DMODEL];           // Q | K | V
__device__ __half g_AOh[(size_t)MROWS*DMODEL];

// ---------------------------------------------------------------------------
__device__ __forceinline__ uint32_t smem_u32(const void* p) {
    uint32_t a;
    asm("{ .reg .u64 t; cvta.to.shared.u64 t, %1; cvt.u32.u64 %0, t; }"
        : "=r"(a) : "l"(p));
    return a;
}

#define LDMX4(r0, r1, r2, r3, addr) \
    asm volatile("ldmatrix.sync.aligned.m8n8.x4.shared.b16 {%0,%1,%2,%3}, [%4];" \
                 : "=r"(r0), "=r"(r1), "=r"(r2), "=r"(r3) : "r"(addr))

#define LDMX4T(r0, r1, r2, r3, addr) \
    asm volatile("ldmatrix.sync.aligned.m8n8.x4.trans.shared.b16 {%0,%1,%2,%3}, [%4];" \
                 : "=r"(r0), "=r"(r1), "=r"(r2), "=r"(r3) : "r"(addr))

#define MMA16816_2(d, a, b0r, b1r) \
    asm volatile("mma.sync.aligned.m16n8k16.row.col.f32.f16.f16.f32 " \
                 "{%0,%1,%2,%3}, {%4,%5,%6,%7}, {%8,%9}, {%0,%1,%2,%3};" \
                 : "+f"((d)[0]), "+f"((d)[1]), "+f"((d)[2]), "+f"((d)[3]) \
                 : "r"((a)[0]), "r"((a)[1]), "r"((a)[2]), "r"((a)[3]), \
                   "r"(b0r), "r"(b1r))

#define CPASYNC16(dst, src) \
    asm volatile("cp.async.cg.shared.global [%0], [%1], 16;" \
                 :: "r"(dst), "l"(src))
#define CPCOMMIT()  asm volatile("cp.async.commit_group;" ::: "memory")
#define CPWAIT(n)   asm volatile("cp.async.wait_group %0;" :: "n"(n) : "memory")

// XOR swizzle for 128B rows: chunk(0..7) ^= row&7 -> conflict-free ldmatrix
__device__ __forceinline__ uint32_t swz128(uint32_t o) {
    return o ^ (((o >> 7) & 7u) << 4);
}

__device__ __forceinline__ uint32_t packh(float a, float b) {
    __half x = __float2half(a), y = __float2half(b);
    return (uint32_t)__half_as_ushort(x) | ((uint32_t)__half_as_ushort(y) << 16);
}

__device__ __forceinline__ void trunc_store(void* hp, float4 v) {
    uint2 hu;
    hu.x = packh(v.x, v.y);
    hu.y = packh(v.z, v.w);
    *reinterpret_cast<uint2*>(hp) = hu;
}

// 2^y on the MUFU pipe (EX2)
__device__ __forceinline__ float exp2m(float y) {
    float r;
    asm("ex2.approx.ftz.f32 %0, %1;" : "=f"(r) : "f"(y));
    return r;
}

// ---------------------------------------------------------------------------
// Pre-truncate / pre-scale helpers
// ---------------------------------------------------------------------------
__global__ void trunc_plain(const float4* __restrict__ in, __half* __restrict__ h) {
    size_t i = (size_t)blockIdx.x * 256 + threadIdx.x;
    trunc_store(h + 4 * i, in[i]);
}

__global__ void trunc_scale4(const float4* __restrict__ in,
                             const float4* __restrict__ sq,
                             const float4* __restrict__ sk,
                             const float4* __restrict__ sv,
                             const float4* __restrict__ so,
                             __half* __restrict__ o0, __half* __restrict__ o1,
                             __half* __restrict__ o2, __half* __restrict__ o3) {
    size_t i = (size_t)blockIdx.x * 256 + threadIdx.x;
    const int k4 = (int)(i & 255);
    float4 v = in[i];
    float4 a = sq[k4], b = sk[k4], c = sv[k4], d = so[k4];
    trunc_store(o0 + 4 * i, make_float4(v.x * a.x, v.y * a.y, v.z * a.z, v.w * a.w));
    trunc_store(o1 + 4 * i, make_float4(v.x * b.x, v.y * b.y, v.z * b.z, v.w * b.w));
    trunc_store(o2 + 4 * i, make_float4(v.x * c.x, v.y * c.y, v.z * c.z, v.w * c.w));
    trunc_store(o3 + 4 * i, make_float4(v.x * d.x, v.y * d.y, v.z * d.z, v.w * d.w));
}

// ---------------------------------------------------------------------------
// Single-fp16 mma.sync GEMM: C[m,n] = sum_k A[m,k]*B[n,k].
// Tile 128x128, BK=64, warp 32x64, 3-stage cp.async, 128B-row swizzle, 2 CTA/SM.
// Loop order: barrier -> issue next copy -> data wait -> compute.
// A-frags double-buffered across k-steps.
// ---------------------------------------------------------------------------
static constexpr int STAGE_B  = 32768;
static constexpr int SMEM_DYN = 3 * STAGE_B;     // 98304

template<int EPI>
__global__ __launch_bounds__(256, 2)
void gemm_fp16(const __half* __restrict__ A, const __half* __restrict__ Bmat,
               float* __restrict__ C, __half* __restrict__ P,
               size_t aStride, size_t bStride, size_t oStride)
{
    extern __shared__ char smem[];
    const __half* Ap = A    + (size_t)blockIdx.z * aStride;
    const __half* Bp = Bmat + (size_t)blockIdx.z * bStride;
    const size_t oofs = (size_t)blockIdx.z * oStride;

    const int tid  = threadIdx.x;
    const int lane = tid & 31;
    const int wid  = tid >> 5;
    const int bm   = blockIdx.y * 128;
    const int bn   = blockIdx.x * 128;
    const int wm0  = (wid & 3) * 32;
    const int wn0  = (wid >> 2) * 64;
    const uint32_t sbase = smem_u32(smem);

    const int arow = tid >> 1;                  // 0..127
    const int acol = (tid & 1) * 4;             // chunk base 0 or 4

    const char* gA = (const char*)Ap + (size_t)(bm + arow) * 2048 + acol * 16;
    const char* gB = (const char*)Bp + (size_t)(bn + arow) * 2048 + acol * 16;
    uint32_t soA[4];
    #pragma unroll
    for (int i = 0; i < 4; ++i)
        soA[i] = swz128((uint32_t)(arow * 128 + (acol + i) * 16));

    auto issue_stage = [&](int c, int s) {
        const size_t k0b = (size_t)c * 128;
        const uint32_t st = sbase + (uint32_t)s * STAGE_B;
        #pragma unroll
        for (int i = 0; i < 4; ++i)
            CPASYNC16(st + soA[i], gA + k0b + i * 16);
        #pragma unroll
        for (int i = 0; i < 4; ++i)
            CPASYNC16(st + 16384u + soA[i], gB + k0b + i * 16);
        CPCOMMIT();
    };

    float acc[2][8][4];
    #pragma unroll
    for (int i = 0; i < 2; ++i)
        #pragma unroll
        for (int j = 0; j < 8; ++j)
            #pragma unroll
            for (int q = 0; q < 4; ++q) acc[i][j][q] = 0.f;

    uint32_t aoff[2], boff[4];
    #pragma unroll
    for (int mt = 0; mt < 2; ++mt)
        aoff[mt] = (uint32_t)((wm0 + mt * 16 + (lane & 15)) * 128 + ((lane >> 4) << 4));
    #pragma unroll
    for (int bb = 0; bb < 4; ++bb)
        boff[bb] = (uint32_t)((wn0 + bb * 16 + (lane & 7) + ((lane >> 4) << 3)) * 128 + ((lane & 8) << 1));

    auto compute = [&](int s) {
        const uint32_t st = sbase + (uint32_t)s * STAGE_B;
        uint32_t af[2][2][4];
        #pragma unroll
        for (int mt = 0; mt < 2; ++mt)
            LDMX4(af[0][mt][0], af[0][mt][1], af[0][mt][2], af[0][mt][3],
                  st + swz128(aoff[mt]));
        #pragma unroll
        for (int ks = 0; ks < 4; ++ks) {
            const int cur = ks & 1;
            uint32_t bf[4][4];
            #pragma unroll
            for (int bb = 0; bb < 4; ++bb)
                LDMX4(bf[bb][0], bf[bb][1], bf[bb][2], bf[bb][3],
                      st + 16384u + swz128(boff[bb] + ks * 32u));
            if (ks < 3) {
                #pragma unroll
                for (int mt = 0; mt < 2; ++mt)
                    LDMX4(af[cur ^ 1][mt][0], af[cur ^ 1][mt][1],
                          af[cur ^ 1][mt][2], af[cur ^ 1][mt][3],
                          st + swz128(aoff[mt] + (ks + 1) * 32u));
            }
            #pragma unroll
            for (int bb = 0; bb < 4; ++bb)
                #pragma unroll
                for (int mt = 0; mt < 2; ++mt) {
                    MMA16816_2(acc[mt][2 * bb],     af[cur][mt], bf[bb][0], bf[bb][1]);
                    MMA16816_2(acc[mt][2 * bb + 1], af[cur][mt], bf[bb][2], bf[bb][3]);
                }
        }
    };

    issue_stage(0, 0);
    issue_stage(1, 1);

    for (int c = 0; c < 16; ++c) {
        __syncthreads();
        if (c + 2 < 16) issue_stage(c + 2, (c + 2) % 3);
        if (c + 2 < 16)      { CPWAIT(2); }
        else if (c + 1 < 16) { CPWAIT(1); }
        else                 { CPWAIT(0); }
        compute(c % 3);
    }

    // ---- epilogue
    #pragma unroll
    for (int mt = 0; mt < 2; ++mt) {
        const int m = bm + wm0 + mt * 16 + (lane >> 2);
        #pragma unroll
        for (int nf = 0; nf < 8; ++nf) {
            const int n = bn + wn0 + nf * 8 + (lane & 3) * 2;
            const size_t o0 = oofs + (size_t)m * DMODEL + n;
            const size_t o1 = oofs + (size_t)(m + 8) * DMODEL + n;
            if (EPI == 0) {
                float2 v0 = {acc[mt][nf][0], acc[mt][nf][1]};
                float2 v1 = {acc[mt][nf][2], acc[mt][nf][3]};
                *reinterpret_cast<float2*>(C + o0) = v0;
                *reinterpret_cast<float2*>(C + o1) = v1;
            } else {
                *reinterpret_cast<uint32_t*>(P + o0) = packh(acc[mt][nf][0], acc[mt][nf][1]);
                *reinterpret_cast<uint32_t*>(P + o1) = packh(acc[mt][nf][2], acc[mt][nf][3]);
            }
        }
    }
}

// ---------------------------------------------------------------------------
// fp16 flash attention: Q/K/V/P single fp16, 2 CTAs/SM, 3-stage cp.async K/V,
// Q smem-direct, EX2 softmax. Loop: barrier -> issue -> wait -> compute.
// ---------------------------------------------------------------------------
static constexpr int RSA    = 72;
static constexpr int QMAT_E = 128 * RSA;
static constexpr int STG_E  = 2 * 64 * RSA;
static constexpr int ASMEM  = (QMAT_E + 3 * STG_E) * 2;   // 73728 bytes

__global__ __launch_bounds__(256, 2)
void attn_mma(const __half* __restrict__ Qh,
              const __half* __restrict__ Kh, const __half* __restrict__ Vh,
              const float* __restrict__ bias,
              __half* __restrict__ AOh)
{
    extern __shared__ __half asmem[];
    const int tid  = threadIdx.x;
    const int lane = tid & 31;
    const int w    = tid >> 5;
    const int qt   = (int)gridDim.x - 1 - (int)blockIdx.x;
    const int h    = blockIdx.y;
    const int b    = blockIdx.z;
    const int q0   = qt * 128;
    const uint32_t sbase = smem_u32(asmem);
    const int nt   = 2 * qt + 2;

    const int krow = tid >> 2;
    const int kseg = (tid & 3) * 32;
    const char* gK = (const char*)(Kh + (size_t)(b * SEQ + krow) * DMODEL + h * DHEAD) + kseg;
    const char* gV = (const char*)(Vh + (size_t)(b * SEQ + krow) * DMODEL + h * DHEAD) + kseg;
    const uint32_t kvoff = (uint32_t)(krow * 144 + kseg);

    auto issue_kv = [&](int kt, int s) {
        const size_t gofs = (size_t)kt * 64 * 2048;
        const uint32_t st = sbase + (uint32_t)(QMAT_E + s * STG_E) * 2;
        CPASYNC16(st + kvoff,              gK + gofs);
        CPASYNC16(st + kvoff + 16,         gK + gofs + 16);
        CPASYNC16(st + 9216u + kvoff,      gV + gofs);
        CPASYNC16(st + 9216u + kvoff + 16, gV + gofs + 16);
        CPCOMMIT();
    };

    issue_kv(0, 0);
    issue_kv(1, 1);

    {
        const __half* Qb = Qh + (size_t)(b * SEQ + q0) * DMODEL + h * DHEAD;
        #pragma unroll
        for (int i = 0; i < 4; ++i) {
            int idx = tid + i * 256;
            int r   = idx >> 3;
            int c16 = idx & 7;
            uint4 v = *reinterpret_cast<const uint4*>(Qb + (size_t)r * DMODEL + c16 * 8);
            *reinterpret_cast<uint4*>(asmem + r * RSA + c16 * 8) = v;
        }
    }
    __syncthreads();

    uint32_t qf[4][4];
    #pragma unroll
    for (int ks = 0; ks < 4; ++ks) {
        const uint32_t off = ((w * 16 + (lane & 15)) * RSA + ks * 16 + ((lane >> 4) << 3)) * 2;
        LDMX4(qf[ks][0], qf[ks][1], qf[ks][2], qf[ks][3], sbase + off);
    }

    float m0 = -1e30f, m1 = -1e30f, l0 = 0.f, l1 = 0.f;
    float o[8][4];
    #pragma unroll
    for (int j = 0; j < 8; ++j)
        #pragma unroll
        for (int q = 0; q < 4; ++q) o[j][q] = 0.f;

    const int q_r0 = q0 + w * 16 + (lane >> 2);
    const int q_r1 = q_r0 + 8;
    const float* bph = bias + (size_t)h * SEQ * SEQ;

    for (int kt = 0; kt < nt; ++kt) {
        const int k0 = kt * 64;
        __syncthreads();
        if (kt + 2 < nt) issue_kv(kt + 2, (kt + 2) % 3);
        if (kt + 2 < nt)      { CPWAIT(2); }
        else if (kt + 1 < nt) { CPWAIT(1); }
        else                  { CPWAIT(0); }

        const uint32_t Khu = sbase + (uint32_t)(QMAT_E + (kt % 3) * STG_E) * 2;
        const uint32_t Vhu = Khu + 9216u;

        float sacc[8][4];
        #pragma unroll
        for (int j = 0; j < 8; ++j)
            #pragma unroll
            for (int q = 0; q < 4; ++q) sacc[j][q] = 0.f;
        #pragma unroll
        for (int ks = 0; ks < 4; ++ks) {
            #pragma unroll
            for (int bb = 0; bb < 4; ++bb) {
                const uint32_t off =
                    ((bb * 16 + (lane & 7) + ((lane >> 4) << 3)) * RSA + ks * 16 + (lane & 8)) * 2;
                uint32_t b0, b1, b2, b3;
                LDMX4(b0, b1, b2, b3, Khu + off);
                MMA16816_2(sacc[2 * bb],     qf[ks], b0, b1);
                MMA16816_2(sacc[2 * bb + 1], qf[ks], b2, b3);
            }
        }

        const bool mask = (kt >= 2 * qt);
        const float* r0p = bph + (size_t)q_r0 * SEQ + k0 + 2 * (lane & 3);
        const float* r1p = bph + (size_t)q_r1 * SEQ + k0 + 2 * (lane & 3);
        #pragma unroll
        for (int nf = 0; nf < 8; ++nf) {
            float2 b0 = *reinterpret_cast<const float2*>(r0p + nf * 8);
            float2 b1 = *reinterpret_cast<const float2*>(r1p + nf * 8);
            float v0 = fmaf(sacc[nf][0], 0.18033688f, b0.x * 1.4426950f);
            float v1 = fmaf(sacc[nf][1], 0.18033688f, b0.y * 1.4426950f);
            float v2 = fmaf(sacc[nf][2], 0.18033688f, b1.x * 1.4426950f);
            float v3 = fmaf(sacc[nf][3], 0.18033688f, b1.y * 1.4426950f);
            if (mask) {
                const int kc = k0 + nf * 8 + 2 * (lane & 3);
                if (kc     > q_r0) v0 = -1e30f;
                if (kc + 1 > q_r0) v1 = -1e30f;
                if (kc     > q_r1) v2 = -1e30f;
                if (kc + 1 > q_r1) v3 = -1e30f;
            }
            sacc[nf][0] = v0; sacc[nf][1] = v1; sacc[nf][2] = v2; sacc[nf][3] = v3;
        }

        float m0n = m0, m1n = m1;
        #pragma unroll
        for (int nf = 0; nf < 8; ++nf) {
            m0n = fmaxf(m0n, fmaxf(sacc[nf][0], sacc[nf][1]));
            m1n = fmaxf(m1n, fmaxf(sacc[nf][2], sacc[nf][3]));
        }
        m0n = fmaxf(m0n, __shfl_xor_sync(0xffffffffu, m0n, 1));
        m0n = fmaxf(m0n, __shfl_xor_sync(0xffffffffu, m0n, 2));
        m1n = fmaxf(m1n, __shfl_xor_sync(0xffffffffu, m1n, 1));
        m1n = fmaxf(m1n, __shfl_xor_sync(0xffffffffu, m1n, 2));
        const float c0 = exp2m(m0 - m0n), c1 = exp2m(m1 - m1n);
        m0 = m0n; m1 = m1n;
        l0 *= c0;  l1 *= c1;
        #pragma unroll
        for (int nf = 0; nf < 8; ++nf) {
            o[nf][0] *= c0; o[nf][1] *= c0;
            o[nf][2] *= c1; o[nf][3] *= c1;
        }

        uint32_t pA0[8], pA1[8];
        #pragma unroll
        for (int nf = 0; nf < 8; ++nf) {
            float p0 = exp2m(sacc[nf][0] - m0);
            float p1 = exp2m(sacc[nf][1] - m0);
            float p2 = exp2m(sacc[nf][2] - m1);
            float p3 = exp2m(sacc[nf][3] - m1);
            l0 += p0 + p1; l1 += p2 + p3;
            pA0[nf] = packh(p0, p1);
            pA1[nf] = packh(p2, p3);
        }

        #pragma unroll
        for (int ks = 0; ks < 4; ++ks) {
            uint32_t ah[4] = { pA0[2 * ks], pA1[2 * ks], pA0[2 * ks + 1], pA1[2 * ks + 1] };
            #pragma unroll
            for (int ng = 0; ng < 4; ++ng) {
                const uint32_t off =
                    ((ks * 16 + (lane & 7) + (lane & 8)) * RSA + ng * 16 + ((lane >> 4) << 3)) * 2;
                uint32_t h0, h1, h2, h3;
                LDMX4T(h0, h1, h2, h3, Vhu + off);
                MMA16816_2(o[2 * ng],     ah, h0, h1);
                MMA16816_2(o[2 * ng + 1], ah, h2, h3);
            }
        }
    }

    l0 += __shfl_xor_sync(0xffffffffu, l0, 1);
    l0 += __shfl_xor_sync(0xffffffffu, l0, 2);
    l1 += __shfl_xor_sync(0xffffffffu, l1, 1);
    l1 += __shfl_xor_sync(0xffffffffu, l1, 2);
    const float i0 = 1.f / l0, i1 = 1.f / l1;
    const size_t r0off = (size_t)(b * SEQ + q_r0) * DMODEL + h * DHEAD + 2 * (lane & 3);
    const size_t r1off = (size_t)(b * SEQ + q_r1) * DMODEL + h * DHEAD + 2 * (lane & 3);
    #pragma unroll
    for (int nf = 0; nf < 8; ++nf) {
        *reinterpret_cast<uint32_t*>(AOh + r0off + nf * 8) = packh(o[nf][0] * i0, o[nf][1] * i0);
        *reinterpret_cast<uint32_t*>(AOh + r1off + nf * 8) = packh(o[nf][2] * i1, o[nf][3] * i1);
    }
}

// ---------------------------------------------------------------------------
extern "C" void kernel_launch(void* const* d_in, const int* in_sizes, int n_in,
                              void* d_out, int out_size)
{
    const float* x     = (const float*)d_in[0];
    const float* basis = (const float*)d_in[1];
    const float* sq    = (const float*)d_in[2];
    const float* sk    = (const float*)d_in[3];
    const float* sv    = (const float*)d_in[4];
    const float* so    = (const float*)d_in[5];
    const float* bias  = (const float*)d_in[6];
    float*       out   = (float*)d_out;

    __half *Xh, *Bmh, *Bs4, *M4, *QKV, *AOh;
    cudaGetSymbolAddress((void**)&Xh,  g_Xh);
    cudaGetSymbolAddress((void**)&Bmh, g_Bmh);
    cudaGetSymbolAddress((void**)&Bs4, g_Bs4);
    cudaGetSymbolAddress((void**)&M4,  g_M4);
    cudaGetSymbolAddress((void**)&QKV, g_QKV);
    cudaGetSymbolAddress((void**)&AOh, g_AOh);

    const size_t SEG  = (size_t)MROWS * DMODEL;
    const size_t BSEG = (size_t)DMODEL * DMODEL;
    __half* Qh = QKV; __half* Kh = QKV + SEG; __half* Vh = QKV + 2 * SEG;
    __half* Mo = M4 + 3 * BSEG;

    cudaFuncSetAttribute(gemm_fp16<0>, cudaFuncAttributeMaxDynamicSharedMemorySize, SMEM_DYN);
    cudaFuncSetAttribute(gemm_fp16<4>, cudaFuncAttributeMaxDynamicSharedMemorySize, SMEM_DYN);
    cudaFuncSetAttribute(attn_mma, cudaFuncAttributeMaxDynamicSharedMemorySize, ASMEM);

    // pre-truncate / pre-scale
    trunc_plain<<<MROWS * DMODEL / 1024, 256>>>((const float4*)x, Xh);
    trunc_plain<<<DMODEL * DMODEL / 1024, 256>>>((const float4*)basis, Bmh);
    trunc_scale4<<<DMODEL * DMODEL / 1024, 256>>>((const float4*)basis,
                                                  (const float4*)sq, (const float4*)sk,
                                                  (const float4*)sv, (const float4*)so,
                                                  Bs4, Bs4 + BSEG, Bs4 + 2 * BSEG, Bs4 + 3 * BSEG);

    // M-build: M_s = (basis*s) @ basis^T, symmetric; all 4 z-batched
    gemm_fp16<4><<<dim3(DMODEL / 128, DMODEL / 128, 4), 256, SMEM_DYN>>>(
        Bs4, Bmh, nullptr, M4, BSEG, 0, BSEG);

    // QKV = X @ M_{q,k,v}
    gemm_fp16<4><<<dim3(DMODEL / 128, MROWS / 128, 3), 256, SMEM_DYN>>>(
        Xh, M4, nullptr, QKV, 0, BSEG, SEG);

    attn_mma<<<dim3(SEQ / 128, NHEADS, BATCH), 256, ASMEM>>>(Qh, Kh, Vh, bias, AOh);

    // out = AO @ M_o (fp32 epilogue)
    gemm_fp16<0><<<dim3(DMODEL / 128, MROWS / 128), 256, SMEM_DYN>>>(
        AOh, Mo, out, nullptr, 0, 0, 0);
}